// round 2
// baseline (speedup 1.0000x reference)
#include <cuda_runtime.h>
#include <math.h>

// ---------------------------------------------------------------------------
// Problem constants: B=4, T=2048, C=1024
// ---------------------------------------------------------------------------
#define BATCH 4
#define SEQ   2048
#define CH    1024
#define MTOT  (BATCH * SEQ)          // 8192

// Scratch (allocation-free: __device__ globals)
__device__ float g_Q[MTOT * CH];     // 32 MB
__device__ float g_K[MTOT * CH];     // 32 MB
__device__ float g_V[MTOT * CH];     // 32 MB
__device__ float g_S[BATCH * SEQ * SEQ];  // 64 MB (scores -> probs in place)
__device__ float g_O[MTOT * CH];     // 32 MB

// ---------------------------------------------------------------------------
// Register-blocked SGEMM: C[M,N] = alpha * A[M,K] @ op(B) (+ bias), optional
// interleaved-pair RoPE epilogue, optional causal block skip (scores GEMM),
// optional causal K-truncation (P@V GEMM, where A rows are zero past diag).
//  TRANSB=false: B is [K,N] row-major.  TRANSB=true: B is [N,K] row-major.
//  blockIdx.z batches via sA/sB/sC element strides.
// ---------------------------------------------------------------------------
#define BM 128
#define BN 128
#define BK 8
#define TM 8
#define TN 8

template<bool TRANSB, bool ROPE, bool CAUSAL_SKIP, bool CAUSAL_KLIM>
__global__ __launch_bounds__(256, 2)
void gemm_f32(const float* __restrict__ A, const float* __restrict__ Bm,
              const float* __restrict__ bias, float* __restrict__ C,
              int M, int N, int K,
              long long sA, long long sB, long long sC,
              float alpha, int T)
{
    __shared__ float As[BK * BM];
    __shared__ float Bs[BK * BN];

    const int m0 = blockIdx.y * BM;
    const int n0 = blockIdx.x * BN;
    if (CAUSAL_SKIP && n0 >= m0 + BM) return;   // block fully above causal diag

    const float* Ab = A  + (long long)blockIdx.z * sA;
    const float* Bb = Bm + (long long)blockIdx.z * sB;
    float*       Cb = C  + (long long)blockIdx.z * sC;

    const int tid = threadIdx.x;
    const int tx  = tid & 15;    // col group (8 cols each)
    const int ty  = tid >> 4;    // row group (8 rows each)

    // A tile loader: 128 rows x 8 cols, one float4 per thread
    const int aRow = tid >> 1;
    const int aCol = (tid & 1) * 4;
    // B tile loaders
    const int bRowNN = tid >> 5;          // 8 x 128 (k, n)
    const int bColNN = (tid & 31) * 4;
    const int bRowNT = tid >> 1;          // 128 x 8 (n, k)
    const int bColNT = (tid & 1) * 4;

    float acc[TM][TN];
    #pragma unroll
    for (int i = 0; i < TM; i++)
        #pragma unroll
        for (int j = 0; j < TN; j++) acc[i][j] = 0.f;

    // P@V: A rows in this block are zero for k >= m0 + BM
    const int Kend = CAUSAL_KLIM ? min(K, m0 + BM) : K;

    for (int k0 = 0; k0 < Kend; k0 += BK) {
        // A -> As (transposed to [k][m])
        float4 av = *reinterpret_cast<const float4*>(
            Ab + (long long)(m0 + aRow) * K + (k0 + aCol));
        As[(aCol + 0) * BM + aRow] = av.x;
        As[(aCol + 1) * BM + aRow] = av.y;
        As[(aCol + 2) * BM + aRow] = av.z;
        As[(aCol + 3) * BM + aRow] = av.w;

        if (!TRANSB) {
            float4 bv = *reinterpret_cast<const float4*>(
                Bb + (long long)(k0 + bRowNN) * N + (n0 + bColNN));
            *reinterpret_cast<float4*>(&Bs[bRowNN * BN + bColNN]) = bv;
        } else {
            float4 bv = *reinterpret_cast<const float4*>(
                Bb + (long long)(n0 + bRowNT) * K + (k0 + bColNT));
            Bs[(bColNT + 0) * BN + bRowNT] = bv.x;
            Bs[(bColNT + 1) * BN + bRowNT] = bv.y;
            Bs[(bColNT + 2) * BN + bRowNT] = bv.z;
            Bs[(bColNT + 3) * BN + bRowNT] = bv.w;
        }
        __syncthreads();

        #pragma unroll
        for (int k = 0; k < BK; k++) {
            float ar[TM], br[TN];
            #pragma unroll
            for (int i = 0; i < TM; i++) ar[i] = As[k * BM + ty * TM + i];
            #pragma unroll
            for (int j = 0; j < TN; j++) br[j] = Bs[k * BN + tx * TN + j];
            #pragma unroll
            for (int i = 0; i < TM; i++)
                #pragma unroll
                for (int j = 0; j < TN; j++)
                    acc[i][j] = fmaf(ar[i], br[j], acc[i][j]);
        }
        __syncthreads();
    }

    // Epilogue
    #pragma unroll
    for (int i = 0; i < TM; i++) {
        const int m = m0 + ty * TM + i;
        float row[TN];
        #pragma unroll
        for (int j = 0; j < TN; j++) {
            float v = acc[i][j] * alpha;
            if (bias) v += bias[n0 + tx * TN + j];
            row[j] = v;
        }
        if (ROPE) {
            const int t = m % T;   // position in sequence
            #pragma unroll
            for (int j = 0; j < TN; j += 2) {
                const int c = n0 + tx * TN + j;           // even channel
                float inv = powf(10000.0f, -(float)c / (float)N);
                float fr  = (float)t * inv;
                float s, cc;
                sincosf(fr, &s, &cc);
                float x0 = row[j], x1 = row[j + 1];
                row[j]     = x0 * cc - x1 * s;
                row[j + 1] = x1 * cc + x0 * s;
            }
        }
        float4* dst = reinterpret_cast<float4*>(Cb + (long long)m * N + n0 + tx * TN);
        dst[0] = make_float4(row[0], row[1], row[2], row[3]);
        dst[1] = make_float4(row[4], row[5], row[6], row[7]);
    }
}

// ---------------------------------------------------------------------------
// Causal row softmax, in place on S. One block per (b, t) row.
// Writes zeros above the diagonal so the subsequent P@V GEMM can be dense
// (within the causal K-range).
// ---------------------------------------------------------------------------
__global__ __launch_bounds__(256)
void softmax_causal(float* __restrict__ S, int T)
{
    const long long row = blockIdx.x;
    const int t = (int)(row % T);
    float* p = S + row * (long long)T;
    const int len = t + 1;
    const int tid = threadIdx.x;

    __shared__ float sh[8];
    __shared__ float bcast;

    float mx = -3.0e38f;
    for (int i = tid; i < len; i += 256) mx = fmaxf(mx, p[i]);
    #pragma unroll
    for (int o = 16; o > 0; o >>= 1) mx = fmaxf(mx, __shfl_xor_sync(0xffffffffu, mx, o));
    if ((tid & 31) == 0) sh[tid >> 5] = mx;
    __syncthreads();
    if (tid == 0) {
        float m = sh[0];
        #pragma unroll
        for (int i = 1; i < 8; i++) m = fmaxf(m, sh[i]);
        bcast = m;
    }
    __syncthreads();
    mx = bcast;

    float sum = 0.f;
    for (int i = tid; i < len; i += 256) {
        float e = expf(p[i] - mx);
        p[i] = e;
        sum += e;
    }
    #pragma unroll
    for (int o = 16; o > 0; o >>= 1) sum += __shfl_xor_sync(0xffffffffu, sum, o);
    __syncthreads();
    if ((tid & 31) == 0) sh[tid >> 5] = sum;
    __syncthreads();
    if (tid == 0) {
        float s = 0.f;
        #pragma unroll
        for (int i = 0; i < 8; i++) s += sh[i];
        bcast = s;
    }
    __syncthreads();
    const float invs = 1.0f / bcast;

    for (int i = tid; i < len; i += 256) p[i] *= invs;
    for (int i = len + tid; i < T; i += 256) p[i] = 0.f;
}

// ---------------------------------------------------------------------------
// kernel_launch
// inputs: x, Wq, bq, Wk, bk, Wv, bv, Wo, bo
// ---------------------------------------------------------------------------
extern "C" void kernel_launch(void* const* d_in, const int* in_sizes, int n_in,
                              void* d_out, int out_size)
{
    const float* x  = (const float*)d_in[0];
    const float* Wq = (const float*)d_in[1];
    const float* bq = (const float*)d_in[2];
    const float* Wk = (const float*)d_in[3];
    const float* bk = (const float*)d_in[4];
    const float* Wv = (const float*)d_in[5];
    const float* bv = (const float*)d_in[6];
    const float* Wo = (const float*)d_in[7];
    const float* bo = (const float*)d_in[8];
    float* out = (float*)d_out;

    float *pQ, *pK, *pV, *pS, *pO;
    cudaGetSymbolAddress((void**)&pQ, g_Q);
    cudaGetSymbolAddress((void**)&pK, g_K);
    cudaGetSymbolAddress((void**)&pV, g_V);
    cudaGetSymbolAddress((void**)&pS, g_S);
    cudaGetSymbolAddress((void**)&pO, g_O);

    const int B = BATCH, T = SEQ, C = CH, M = MTOT;
    const long long sTC = (long long)T * C;
    const long long sTT = (long long)T * T;

    dim3 blk(256);
    dim3 gridProj(C / BN, M / BM, 1);       // 8 x 64
    dim3 gridS(T / BN, T / BM, B);          // 16 x 16 x 4
    dim3 gridPV(C / BN, T / BM, B);         // 8 x 16 x 4

    // Q = rope(x @ Wq + bq), K = rope(x @ Wk + bk), V = x @ Wv + bv
    gemm_f32<false, true,  false, false><<<gridProj, blk>>>(x, Wq, bq, pQ, M, C, C, 0, 0, 0, 1.0f, T);
    gemm_f32<false, true,  false, false><<<gridProj, blk>>>(x, Wk, bk, pK, M, C, C, 0, 0, 0, 1.0f, T);
    gemm_f32<false, false, false, false><<<gridProj, blk>>>(x, Wv, bv, pV, M, C, C, 0, 0, 0, 1.0f, T);

    // S = Q @ K^T / sqrt(C)  (causal blocks only)
    gemm_f32<true, false, true, false><<<gridS, blk>>>(pQ, pK, nullptr, pS, T, T, C,
                                                       sTC, sTC, sTT, 0.03125f, T);

    // causal softmax in place
    softmax_causal<<<B * T, blk>>>(pS, T);

    // O = P @ V  (K-loop truncated at causal diagonal)
    gemm_f32<false, false, false, true><<<gridPV, blk>>>(pS, pV, nullptr, pO, T, C, T,
                                                         sTT, sTC, sTC, 1.0f, T);

    // out = O @ Wo + bo
    gemm_f32<false, false, false, false><<<gridProj, blk>>>(pO, Wo, bo, out, M, C, C,
                                                            0, 0, 0, 1.0f, T);
}

// round 7
// speedup vs baseline: 1.0339x; 1.0339x over previous
#include <cuda_runtime.h>
#include <cuda_bf16.h>
#include <math.h>
#include <stdint.h>

// ---------------------------------------------------------------------------
// Problem: B=4, T=2048, C=1024.  out = softmax(causal(QK^T/32)) V Wo + bo
// Tensor path: mma.sync bf16 (baseline sm_100 PTX; tcgen05 unavailable here)
// bf16x3 split for fp32-grade accuracy.
// ---------------------------------------------------------------------------
#define BATCH 4
#define SEQ   2048
#define CH    1024
#define MTOT  (BATCH * SEQ)

__device__ float g_Q[MTOT * CH];
__device__ float g_K[MTOT * CH];
__device__ float g_V[MTOT * CH];
__device__ float g_S[BATCH * SEQ * SEQ];
__device__ float g_O[MTOT * CH];

#define TILE_M 128
#define TILE_N 128
#define BK     32
#define NTHREADS 256

// smem: 4 matrices (Ah, Al, Bh, Bl), each 128 rows x 32 bf16.
// Row stride 80 B: multiple of 16 (ldmatrix alignment requirement) and
// 8-row ldmatrix address set {r*80 mod 128} = {0,80,32,112,64,16,96,48}
// covers distinct 16B slots -> conflict-free.
#define ROWB   80
#define MATB   (128 * ROWB)          // 10240
#define OFF_AH 0
#define OFF_AL (MATB)
#define OFF_BH (2 * MATB)
#define OFF_BL (3 * MATB)
#define STAGEB (4 * MATB)            // 40960
#define SMEM_TOTAL (2 * STAGEB)      // 81920

__device__ __forceinline__ uint32_t smem_u32(const void* p) {
    uint32_t a;
    asm("{ .reg .u64 t; cvta.to.shared.u64 t, %1; cvt.u32.u64 %0, t; }" : "=r"(a) : "l"(p));
    return a;
}

__device__ __forceinline__ void ldsm4(uint32_t* r, uint32_t addr) {
    asm volatile("ldmatrix.sync.aligned.m8n8.x4.shared.b16 {%0,%1,%2,%3}, [%4];"
                 : "=r"(r[0]), "=r"(r[1]), "=r"(r[2]), "=r"(r[3]) : "r"(addr));
}

__device__ __forceinline__ void mma16816(float* d, const uint32_t* a, uint32_t b0, uint32_t b1) {
    asm volatile(
        "mma.sync.aligned.m16n8k16.row.col.f32.bf16.bf16.f32 "
        "{%0,%1,%2,%3},{%4,%5,%6,%7},{%8,%9},{%0,%1,%2,%3};"
        : "+f"(d[0]), "+f"(d[1]), "+f"(d[2]), "+f"(d[3])
        : "r"(a[0]), "r"(a[1]), "r"(a[2]), "r"(a[3]), "r"(b0), "r"(b1));
}

__device__ __forceinline__ void cvt_split(float x, __nv_bfloat16& h, __nv_bfloat16& l) {
    h = __float2bfloat16(x);
    l = __float2bfloat16(x - __bfloat162float(h));
}

__device__ __forceinline__ void st_hl(char* base_h, char* base_l, uint32_t off,
                                      float a, float b) {
    __nv_bfloat16 h0, l0, h1, l1;
    cvt_split(a, h0, l0); cvt_split(b, h1, l1);
    *reinterpret_cast<__nv_bfloat162*>(base_h + off) = {h0, h1};
    *reinterpret_cast<__nv_bfloat162*>(base_l + off) = {l0, l1};
}

// ---------------------------------------------------------------------------
// C[M,N] = alpha * A @ B^T (+bias) (+RoPE epilogue)
//  A: [M,K] fp32 row-major.
//  TRANSB=false: B source [N,K] row-major (direct K-major copy)
//  TRANSB=true : B source [K,N] row-major (transpose during smem store)
// ---------------------------------------------------------------------------
template<bool TRANSB, bool ROPE, bool CAUSAL_SKIP, bool CAUSAL_KLIM>
__global__ __launch_bounds__(NTHREADS, 1)
void gemm_tc(const float* __restrict__ A, const float* __restrict__ Bm,
             const float* __restrict__ bias, float* __restrict__ C,
             int M, int N, int K,
             long long sA, long long sB, long long sC, float alpha)
{
    extern __shared__ __align__(256) char smem[];
    const uint32_t sbase = smem_u32(smem);

    const int m0 = blockIdx.y * TILE_M;
    const int n0 = blockIdx.x * TILE_N;
    if (CAUSAL_SKIP && n0 >= m0 + TILE_M) return;

    const float* Ab = A  + (long long)blockIdx.z * sA;
    const float* Bb = Bm + (long long)blockIdx.z * sB;
    float*       Cb = C  + (long long)blockIdx.z * sC;

    const int tid = threadIdx.x;
    const int wid = tid >> 5;
    const int lid = tid & 31;
    const int warp_m = wid >> 2;      // 0..1 -> 64-row slab
    const int warp_n = wid & 3;       // 0..3 -> 32-col slab

    float acc[4][4][4];
    #pragma unroll
    for (int i = 0; i < 4; i++)
        #pragma unroll
        for (int j = 0; j < 4; j++)
            #pragma unroll
            for (int k = 0; k < 4; k++) acc[i][j][k] = 0.f;

    const int Kend  = CAUSAL_KLIM ? (m0 + TILE_M) : K;
    const int NITER = Kend / BK;

    // ldmatrix lane address components (within a matrix, row stride ROWB)
    const int a_r = (lid & 15);               // + mt*16 + warp_m*64
    const int a_c = (lid >> 4) << 3;          // + kk
    const int b_r = (lid & 7) + ((lid >> 4) << 3);   // + nt16*16 + warp_n*32
    const int b_c = ((lid >> 3) & 1) << 3;           // + kk

    for (int it = 0; it < NITER; ++it) {
        char* stage = smem + (it & 1) * STAGEB;
        const uint32_t sstage = sbase + (it & 1) * STAGEB;
        const int kc = it * BK;

        // ---- A tile: 128 x 32 fp32, k-contiguous float4 (1024 float4s) ----
        #pragma unroll
        for (int i = 0; i < 4; ++i) {
            const int fl = tid + i * NTHREADS;
            const int r  = fl >> 3;
            const int kq = (fl & 7) << 2;
            float4 v = *reinterpret_cast<const float4*>(
                Ab + (size_t)(m0 + r) * K + kc + kq);
            const uint32_t off = (uint32_t)(r * ROWB + kq * 2);
            st_hl(stage + OFF_AH, stage + OFF_AL, off,     v.x, v.y);
            st_hl(stage + OFF_AH, stage + OFF_AL, off + 4, v.z, v.w);
        }
        // ---- B tile ----
        if (!TRANSB) {
            #pragma unroll
            for (int i = 0; i < 4; ++i) {
                const int fl = tid + i * NTHREADS;
                const int r  = fl >> 3;
                const int kq = (fl & 7) << 2;
                float4 v = *reinterpret_cast<const float4*>(
                    Bb + (size_t)(n0 + r) * K + kc + kq);
                const uint32_t off = (uint32_t)(r * ROWB + kq * 2);
                st_hl(stage + OFF_BH, stage + OFF_BL, off,     v.x, v.y);
                st_hl(stage + OFF_BH, stage + OFF_BL, off + 4, v.z, v.w);
            }
        } else {
            #pragma unroll
            for (int i = 0; i < 4; ++i) {
                const int fl = tid + i * NTHREADS;
                const int kr = fl >> 5;           // 0..31
                const int nq = (fl & 31) << 2;    // 0..124
                float4 v = *reinterpret_cast<const float4*>(
                    Bb + (size_t)(kc + kr) * N + n0 + nq);
                float f[4] = {v.x, v.y, v.z, v.w};
                #pragma unroll
                for (int j = 0; j < 4; ++j) {
                    __nv_bfloat16 h, l;
                    cvt_split(f[j], h, l);
                    const uint32_t off = (uint32_t)((nq + j) * ROWB + kr * 2);
                    *reinterpret_cast<__nv_bfloat16*>(stage + OFF_BH + off) = h;
                    *reinterpret_cast<__nv_bfloat16*>(stage + OFF_BL + off) = l;
                }
            }
        }
        __syncthreads();

        // ---- compute: 2 k16 substeps ----
        #pragma unroll
        for (int kk = 0; kk < BK; kk += 16) {
            uint32_t ah[16], al[16], bh[8], bl[8];
            #pragma unroll
            for (int mt = 0; mt < 4; ++mt) {
                const uint32_t addr = sstage + OFF_AH +
                    (uint32_t)((warp_m * 64 + mt * 16 + a_r) * ROWB + (kk + a_c) * 2);
                ldsm4(ah + mt * 4, addr);
                ldsm4(al + mt * 4, addr + (OFF_AL - OFF_AH));
            }
            #pragma unroll
            for (int nt = 0; nt < 2; ++nt) {
                const uint32_t addr = sstage + OFF_BH +
                    (uint32_t)((warp_n * 32 + nt * 16 + b_r) * ROWB + (kk + b_c) * 2);
                ldsm4(bh + nt * 4, addr);
                ldsm4(bl + nt * 4, addr + (OFF_BL - OFF_BH));
            }
            #pragma unroll
            for (int mt = 0; mt < 4; ++mt)
                #pragma unroll
                for (int nt = 0; nt < 4; ++nt) {
                    const uint32_t* bhp = &bh[(nt >> 1) * 4 + (nt & 1) * 2];
                    const uint32_t* blp = &bl[(nt >> 1) * 4 + (nt & 1) * 2];
                    mma16816(acc[mt][nt], ah + mt * 4, bhp[0], bhp[1]);  // hi*hi
                    mma16816(acc[mt][nt], al + mt * 4, bhp[0], bhp[1]);  // lo*hi
                    mma16816(acc[mt][nt], ah + mt * 4, blp[0], blp[1]);  // hi*lo
                }
        }
        __syncthreads();
    }

    // ---- epilogue ----
    // acc[mt][nt] = {r0c0, r0c1, r1c0, r1c1}; r0 = lid>>2, r1 = r0+8;
    // c0 = (lid&3)*2 (even), c1 = c0+1.
    const int mbase = m0 + warp_m * 64 + (lid >> 2);
    const int nbase = n0 + warp_n * 32 + (lid & 3) * 2;

    float binv[4];        // per-nt RoPE inv_freq cache
    #pragma unroll
    for (int nt = 0; nt < 4; ++nt) {
        if (ROPE) {
            const int c = nbase + nt * 8;
            binv[nt] = powf(10000.0f, -(float)c / (float)N);
        }
    }

    #pragma unroll
    for (int mt = 0; mt < 4; ++mt) {
        #pragma unroll
        for (int h = 0; h < 2; ++h) {
            const int m = mbase + mt * 16 + h * 8;
            const int t = m & (SEQ - 1);
            #pragma unroll
            for (int nt = 0; nt < 4; ++nt) {
                const int n = nbase + nt * 8;
                float v0 = acc[mt][nt][h * 2 + 0] * alpha;
                float v1 = acc[mt][nt][h * 2 + 1] * alpha;
                if (bias) { v0 += bias[n]; v1 += bias[n + 1]; }
                if (ROPE) {
                    float s, co;
                    sincosf((float)t * binv[nt], &s, &co);
                    const float x0 = v0, x1 = v1;
                    v0 = x0 * co - x1 * s;
                    v1 = x1 * co + x0 * s;
                }
                *reinterpret_cast<float2*>(Cb + (size_t)m * N + n) = make_float2(v0, v1);
            }
        }
    }
}

// ---------------------------------------------------------------------------
// Causal row softmax, in place. One block per (b,t) row; zero-fills above diag.
// ---------------------------------------------------------------------------
__global__ __launch_bounds__(256)
void softmax_causal(float* __restrict__ S, int T)
{
    const long long row = blockIdx.x;
    const int t = (int)(row % T);
    float* p = S + row * (long long)T;
    const int len = t + 1;
    const int tid = threadIdx.x;

    __shared__ float sh[8];
    __shared__ float bcast;

    float mx = -3.0e38f;
    for (int i = tid; i < len; i += 256) mx = fmaxf(mx, p[i]);
    #pragma unroll
    for (int o = 16; o > 0; o >>= 1) mx = fmaxf(mx, __shfl_xor_sync(0xffffffffu, mx, o));
    if ((tid & 31) == 0) sh[tid >> 5] = mx;
    __syncthreads();
    if (tid == 0) {
        float m = sh[0];
        #pragma unroll
        for (int i = 1; i < 8; i++) m = fmaxf(m, sh[i]);
        bcast = m;
    }
    __syncthreads();
    mx = bcast;

    float sum = 0.f;
    for (int i = tid; i < len; i += 256) {
        float e = expf(p[i] - mx);
        p[i] = e;
        sum += e;
    }
    #pragma unroll
    for (int o = 16; o > 0; o >>= 1) sum += __shfl_xor_sync(0xffffffffu, sum, o);
    __syncthreads();
    if ((tid & 31) == 0) sh[tid >> 5] = sum;
    __syncthreads();
    if (tid == 0) {
        float s = 0.f;
        #pragma unroll
        for (int i = 0; i < 8; i++) s += sh[i];
        bcast = s;
    }
    __syncthreads();
    const float invs = 1.0f / bcast;

    for (int i = tid; i < len; i += 256) p[i] *= invs;
    for (int i = len + tid; i < T; i += 256) p[i] = 0.f;
}

// ---------------------------------------------------------------------------
// kernel_launch: x, Wq, bq, Wk, bk, Wv, bv, Wo, bo
// ---------------------------------------------------------------------------
extern "C" void kernel_launch(void* const* d_in, const int* in_sizes, int n_in,
                              void* d_out, int out_size)
{
    const float* x  = (const float*)d_in[0];
    const float* Wq = (const float*)d_in[1];
    const float* bq = (const float*)d_in[2];
    const float* Wk = (const float*)d_in[3];
    const float* bk = (const float*)d_in[4];
    const float* Wv = (const float*)d_in[5];
    const float* bv = (const float*)d_in[6];
    const float* Wo = (const float*)d_in[7];
    const float* bo = (const float*)d_in[8];
    float* out = (float*)d_out;

    float *pQ, *pK, *pV, *pS, *pO;
    cudaGetSymbolAddress((void**)&pQ, g_Q);
    cudaGetSymbolAddress((void**)&pK, g_K);
    cudaGetSymbolAddress((void**)&pV, g_V);
    cudaGetSymbolAddress((void**)&pS, g_S);
    cudaGetSymbolAddress((void**)&pO, g_O);

    const int B = BATCH, T = SEQ, C = CH, M = MTOT;
    const long long sTC = (long long)T * C;
    const long long sTT = (long long)T * T;

    cudaFuncSetAttribute(gemm_tc<true,  true,  false, false>, cudaFuncAttributeMaxDynamicSharedMemorySize, SMEM_TOTAL);
    cudaFuncSetAttribute(gemm_tc<true,  false, false, false>, cudaFuncAttributeMaxDynamicSharedMemorySize, SMEM_TOTAL);
    cudaFuncSetAttribute(gemm_tc<false, false, true,  false>, cudaFuncAttributeMaxDynamicSharedMemorySize, SMEM_TOTAL);
    cudaFuncSetAttribute(gemm_tc<true,  false, false, true >, cudaFuncAttributeMaxDynamicSharedMemorySize, SMEM_TOTAL);

    dim3 blk(NTHREADS);
    dim3 gridProj(C / TILE_N, M / TILE_M, 1);   // 8 x 64
    dim3 gridS(T / TILE_N, T / TILE_M, B);      // 16 x 16 x 4
    dim3 gridPV(C / TILE_N, T / TILE_M, B);     // 8 x 16 x 4

    gemm_tc<true, true,  false, false><<<gridProj, blk, SMEM_TOTAL>>>(x, Wq, bq, pQ, M, C, C, 0, 0, 0, 1.0f);
    gemm_tc<true, true,  false, false><<<gridProj, blk, SMEM_TOTAL>>>(x, Wk, bk, pK, M, C, C, 0, 0, 0, 1.0f);
    gemm_tc<true, false, false, false><<<gridProj, blk, SMEM_TOTAL>>>(x, Wv, bv, pV, M, C, C, 0, 0, 0, 1.0f);

    gemm_tc<false, false, true, false><<<gridS, blk, SMEM_TOTAL>>>(pQ, pK, nullptr, pS, T, T, C,
                                                                   sTC, sTC, sTT, 0.03125f);

    softmax_causal<<<B * T, blk>>>(pS, T);

    gemm_tc<true, false, false, true><<<gridPV, blk, SMEM_TOTAL>>>(pS, pV, nullptr, pO, T, C, T,
                                                                   sTT, sTC, sTC, 1.0f);

    gemm_tc<true, false, false, false><<<gridProj, blk, SMEM_TOTAL>>>(pO, Wo, bo, out, M, C, C,
                                                                      0, 0, 0, 1.0f);
}

// round 8
// speedup vs baseline: 2.7610x; 2.6704x over previous
#include <cuda_runtime.h>
#include <cuda_bf16.h>
#include <math.h>
#include <stdint.h>

// ---------------------------------------------------------------------------
// B=4, T=2048, C=1024.  out = softmax(causal(QK^T/32)) V Wo + bo
// mma.sync bf16 with bf16x3 split (hi*hi + lo*hi + hi*lo), fp32 accum.
// All operands pre-split to bf16 hi/lo in gmem; GEMM loop is cp.async-only.
// ---------------------------------------------------------------------------
#define BATCH 4
#define SEQ   2048
#define CH    1024
#define MTOT  (BATCH * SEQ)

typedef __nv_bfloat16 bf16;
typedef __nv_bfloat162 bf162;

// bf16 hi/lo scratch
__device__ bf16 g_xh[MTOT * CH], g_xl[MTOT * CH];
__device__ bf16 g_Wqh[CH * CH], g_Wql[CH * CH];
__device__ bf16 g_Wkh[CH * CH], g_Wkl[CH * CH];
__device__ bf16 g_Wvh[CH * CH], g_Wvl[CH * CH];
__device__ bf16 g_Woh[CH * CH], g_Wol[CH * CH];
__device__ bf16 g_Qh[MTOT * CH], g_Ql[MTOT * CH];
__device__ bf16 g_Kh[MTOT * CH], g_Kl[MTOT * CH];
__device__ bf16 g_Vh[MTOT * CH], g_Vl[MTOT * CH];
__device__ bf16 g_Oh[MTOT * CH], g_Ol[MTOT * CH];
__device__ float g_S[BATCH * SEQ * SEQ];
__device__ bf16 g_Ph[BATCH * SEQ * SEQ], g_Pl[BATCH * SEQ * SEQ];

#define TILE_M 128
#define TILE_N 128
#define BK     32
#define NTHREADS 256

// smem tiles: A (k-major, 128r x 32k, row stride 80B), B either k-major
// (same) or n-major (32k x 128n, row stride 272B). Both strides are 16B
// multiples (ldmatrix alignment) and conflict-free for their access pattern.
#define AROW  80
#define AMAT  10240
#define OFF_AH 0
#define OFF_AL AMAT
#define OFF_BH (2 * AMAT)
#define STAGE 40960
#define NSTAGE 3
#define SMEM_TOTAL (NSTAGE * STAGE)   // 122880

__device__ __forceinline__ uint32_t smem_u32(const void* p) {
    uint32_t a;
    asm("{ .reg .u64 t; cvta.to.shared.u64 t, %1; cvt.u32.u64 %0, t; }" : "=r"(a) : "l"(p));
    return a;
}
#define CP16(dst, src) asm volatile("cp.async.cg.shared.global [%0], [%1], 16;" :: "r"(dst), "l"(src))
#define CP_COMMIT()    asm volatile("cp.async.commit_group;" ::: "memory")
#define CP_WAIT1()     asm volatile("cp.async.wait_group 1;" ::: "memory")

__device__ __forceinline__ void ldsm4(uint32_t* r, uint32_t addr) {
    asm volatile("ldmatrix.sync.aligned.m8n8.x4.shared.b16 {%0,%1,%2,%3}, [%4];"
                 : "=r"(r[0]), "=r"(r[1]), "=r"(r[2]), "=r"(r[3]) : "r"(addr));
}
__device__ __forceinline__ void ldsm4t(uint32_t* r, uint32_t addr) {
    asm volatile("ldmatrix.sync.aligned.m8n8.x4.trans.shared.b16 {%0,%1,%2,%3}, [%4];"
                 : "=r"(r[0]), "=r"(r[1]), "=r"(r[2]), "=r"(r[3]) : "r"(addr));
}
__device__ __forceinline__ void mma16816(float* d, const uint32_t* a, uint32_t b0, uint32_t b1) {
    asm volatile(
        "mma.sync.aligned.m16n8k16.row.col.f32.bf16.bf16.f32 "
        "{%0,%1,%2,%3},{%4,%5,%6,%7},{%8,%9},{%0,%1,%2,%3};"
        : "+f"(d[0]), "+f"(d[1]), "+f"(d[2]), "+f"(d[3])
        : "r"(a[0]), "r"(a[1]), "r"(a[2]), "r"(a[3]), "r"(b0), "r"(b1));
}
__device__ __forceinline__ void cvt_split(float x, bf16& h, bf16& l) {
    h = __float2bfloat16(x);
    l = __float2bfloat16(x - __bfloat162float(h));
}

// ---------------------------------------------------------------------------
// fp32 -> (hi, lo) bf16 split, vectorized
// ---------------------------------------------------------------------------
__global__ void split_f32(const float* __restrict__ s, bf16* __restrict__ h,
                          bf16* __restrict__ l, int n)
{
    const int i = 4 * (blockIdx.x * blockDim.x + threadIdx.x);
    if (i >= n) return;
    float4 v = *reinterpret_cast<const float4*>(s + i);
    bf16 h0, l0, h1, l1, h2, l2, h3, l3;
    cvt_split(v.x, h0, l0); cvt_split(v.y, h1, l1);
    cvt_split(v.z, h2, l2); cvt_split(v.w, h3, l3);
    *reinterpret_cast<bf162*>(h + i)     = {h0, h1};
    *reinterpret_cast<bf162*>(h + i + 2) = {h2, h3};
    *reinterpret_cast<bf162*>(l + i)     = {l0, l1};
    *reinterpret_cast<bf162*>(l + i + 2) = {l2, l3};
}

// ---------------------------------------------------------------------------
// C = alpha * A @ op(B) (+bias) (+RoPE)
//  A: [M,K] bf16 hi/lo, k-major.
//  BN=false: B [N,K] k-major (non-trans ldmatrix).
//  BN=true : B [K,N] n-major (ldmatrix.trans).
//  EPI16: write hi/lo bf16 outputs; else fp32.
// ---------------------------------------------------------------------------
template<bool BN, bool ROPE, bool CSKIP, bool CKLIM, bool EPI16>
__global__ __launch_bounds__(NTHREADS, 1)
void gemm_bf3(const bf16* __restrict__ Ah, const bf16* __restrict__ Al,
              const bf16* __restrict__ Bh, const bf16* __restrict__ Bl,
              const float* __restrict__ bias,
              float* __restrict__ Cf, bf16* __restrict__ Ch, bf16* __restrict__ Cl,
              int M, int N, int K,
              long long sA, long long sB, long long sC, float alpha)
{
    constexpr int BMAT   = BN ? 8704 : 10240;   // 32*272 or 128*80
    constexpr int BROW   = BN ? 272 : 80;
    constexpr int OFF_BL = OFF_BH + BMAT;

    extern __shared__ __align__(256) char smem[];
    const uint32_t sbase = smem_u32(smem);

    const int m0 = blockIdx.y * TILE_M;
    const int n0 = blockIdx.x * TILE_N;
    if (CSKIP && n0 >= m0 + TILE_M) return;

    const bf16* Ahb = Ah + (long long)blockIdx.z * sA;
    const bf16* Alb = Al + (long long)blockIdx.z * sA;
    const bf16* Bhb = Bh + (long long)blockIdx.z * sB;
    const bf16* Blb = Bl + (long long)blockIdx.z * sB;

    const int tid = threadIdx.x;
    const int wid = tid >> 5;
    const int lid = tid & 31;
    const int warp_m = wid >> 2;
    const int warp_n = wid & 3;

    const int Kend  = CKLIM ? (m0 + TILE_M) : K;
    const int NITER = Kend / BK;

    float acc[4][4][4];
    #pragma unroll
    for (int i = 0; i < 4; i++)
        #pragma unroll
        for (int j = 0; j < 4; j++)
            #pragma unroll
            for (int k = 0; k < 4; k++) acc[i][j][k] = 0.f;

    // async stage loader
    auto issue = [&](int it) {
        if (it < NITER) {
            const uint32_t sb = sbase + (it % NSTAGE) * STAGE;
            const int kc = it * BK;
            #pragma unroll
            for (int i = 0; i < 2; ++i) {                 // A: 512 chunks
                const int c  = tid + i * NTHREADS;
                const int r  = c >> 2;
                const int ch = c & 3;
                const size_t g = (size_t)(m0 + r) * K + kc + ch * 8;
                const uint32_t so = (uint32_t)(r * AROW + ch * 16);
                CP16(sb + OFF_AH + so, Ahb + g);
                CP16(sb + OFF_AL + so, Alb + g);
            }
            if (!BN) {
                #pragma unroll
                for (int i = 0; i < 2; ++i) {             // B k-major
                    const int c  = tid + i * NTHREADS;
                    const int r  = c >> 2;
                    const int ch = c & 3;
                    const size_t g = (size_t)(n0 + r) * K + kc + ch * 8;
                    const uint32_t so = (uint32_t)(r * BROW + ch * 16);
                    CP16(sb + OFF_BH + so, Bhb + g);
                    CP16(sb + OFF_BL + so, Blb + g);
                }
            } else {
                #pragma unroll
                for (int i = 0; i < 2; ++i) {             // B n-major: 32k x 128n
                    const int c  = tid + i * NTHREADS;
                    const int kr = c >> 4;
                    const int ch = c & 15;
                    const size_t g = (size_t)(kc + kr) * N + n0 + ch * 8;
                    const uint32_t so = (uint32_t)(kr * BROW + ch * 16);
                    CP16(sb + OFF_BH + so, Bhb + g);
                    CP16(sb + OFF_BL + so, Blb + g);
                }
            }
        }
        CP_COMMIT();
    };

    // ldmatrix lane addressing
    const int a_r = (lid & 15);
    const int a_c = (lid >> 4) << 3;
    const int b_r = (lid & 7) + ((lid >> 4) << 3);       // k-major B
    const int b_c = ((lid >> 3) & 1) << 3;
    const int t_k = (lid & 7) + (((lid >> 3) & 1) << 3); // n-major (trans) B
    const int t_n = (lid >> 4) << 3;

    issue(0);
    issue(1);

    for (int it = 0; it < NITER; ++it) {
        CP_WAIT1();
        __syncthreads();
        const uint32_t sstage = sbase + (it % NSTAGE) * STAGE;

        #pragma unroll
        for (int kk = 0; kk < BK; kk += 16) {
            uint32_t ah[16], al[16], bh[8], bl[8];
            #pragma unroll
            for (int mt = 0; mt < 4; ++mt) {
                const uint32_t addr = sstage + OFF_AH +
                    (uint32_t)((warp_m * 64 + mt * 16 + a_r) * AROW + (kk + a_c) * 2);
                ldsm4(ah + mt * 4, addr);
                ldsm4(al + mt * 4, addr + AMAT);
            }
            if (!BN) {
                #pragma unroll
                for (int nt = 0; nt < 2; ++nt) {
                    const uint32_t addr = sstage + OFF_BH +
                        (uint32_t)((warp_n * 32 + nt * 16 + b_r) * BROW + (kk + b_c) * 2);
                    ldsm4(bh + nt * 4, addr);
                    ldsm4(bl + nt * 4, addr + BMAT);
                }
            } else {
                #pragma unroll
                for (int p = 0; p < 2; ++p) {
                    const uint32_t addr = sstage + OFF_BH +
                        (uint32_t)((kk + t_k) * BROW + (warp_n * 32 + p * 16 + t_n) * 2);
                    ldsm4t(bh + p * 4, addr);
                    ldsm4t(bl + p * 4, addr + BMAT);
                }
            }
            #pragma unroll
            for (int mt = 0; mt < 4; ++mt)
                #pragma unroll
                for (int nt = 0; nt < 4; ++nt) {
                    const uint32_t* bhp = &bh[(nt >> 1) * 4 + (nt & 1) * 2];
                    const uint32_t* blp = &bl[(nt >> 1) * 4 + (nt & 1) * 2];
                    mma16816(acc[mt][nt], ah + mt * 4, bhp[0], bhp[1]);
                    mma16816(acc[mt][nt], al + mt * 4, bhp[0], bhp[1]);
                    mma16816(acc[mt][nt], ah + mt * 4, blp[0], blp[1]);
                }
        }
        issue(it + 2);
    }

    // ---- epilogue ----
    const int mbase = m0 + warp_m * 64 + (lid >> 2);
    const int nbase = n0 + warp_n * 32 + (lid & 3) * 2;

    float binv[4];
    #pragma unroll
    for (int nt = 0; nt < 4; ++nt)
        if (ROPE) binv[nt] = powf(10000.0f, -(float)(nbase + nt * 8) / (float)N);

    #pragma unroll
    for (int mt = 0; mt < 4; ++mt) {
        #pragma unroll
        for (int h = 0; h < 2; ++h) {
            const int m = mbase + mt * 16 + h * 8;
            const int t = m & (SEQ - 1);
            #pragma unroll
            for (int nt = 0; nt < 4; ++nt) {
                const int n = nbase + nt * 8;
                float v0 = acc[mt][nt][h * 2 + 0] * alpha;
                float v1 = acc[mt][nt][h * 2 + 1] * alpha;
                if (bias) { v0 += bias[n]; v1 += bias[n + 1]; }
                if (ROPE) {
                    float s, co;
                    sincosf((float)t * binv[nt], &s, &co);
                    const float x0 = v0, x1 = v1;
                    v0 = x0 * co - x1 * s;
                    v1 = x1 * co + x0 * s;
                }
                const size_t off = (size_t)m * N + n + (size_t)blockIdx.z * sC;
                if (EPI16) {
                    bf16 h0, l0, h1, l1;
                    cvt_split(v0, h0, l0); cvt_split(v1, h1, l1);
                    *reinterpret_cast<bf162*>(Ch + off) = {h0, h1};
                    *reinterpret_cast<bf162*>(Cl + off) = {l0, l1};
                } else {
                    *reinterpret_cast<float2*>(Cf + off) = make_float2(v0, v1);
                }
            }
        }
    }
}

// ---------------------------------------------------------------------------
// Causal softmax: reads fp32 S row, writes hi/lo bf16 P row; zero-fills only
// up to the causal 128-block boundary (all the PV GEMM ever reads).
// ---------------------------------------------------------------------------
__global__ __launch_bounds__(256)
void softmax_split(float* __restrict__ S, bf16* __restrict__ Ph,
                   bf16* __restrict__ Pl, int T)
{
    const long long row = blockIdx.x;
    const int t = (int)(row % T);
    float* s = S + row * (long long)T;
    bf16* ph = Ph + row * (long long)T;
    bf16* pl = Pl + row * (long long)T;
    const int len  = t + 1;
    const int zlim = ((t >> 7) + 1) << 7;   // next multiple of 128
    const int tid = threadIdx.x;

    __shared__ float sh[8];
    __shared__ float bcast;

    float mx = -3.0e38f;
    for (int i = tid; i < len; i += 256) mx = fmaxf(mx, s[i]);
    #pragma unroll
    for (int o = 16; o > 0; o >>= 1) mx = fmaxf(mx, __shfl_xor_sync(0xffffffffu, mx, o));
    if ((tid & 31) == 0) sh[tid >> 5] = mx;
    __syncthreads();
    if (tid == 0) {
        float m = sh[0];
        #pragma unroll
        for (int i = 1; i < 8; i++) m = fmaxf(m, sh[i]);
        bcast = m;
    }
    __syncthreads();
    mx = bcast;

    float sum = 0.f;
    for (int i = tid; i < len; i += 256) {
        float e = expf(s[i] - mx);
        s[i] = e;
        sum += e;
    }
    #pragma unroll
    for (int o = 16; o > 0; o >>= 1) sum += __shfl_xor_sync(0xffffffffu, sum, o);
    __syncthreads();
    if ((tid & 31) == 0) sh[tid >> 5] = sum;
    __syncthreads();
    if (tid == 0) {
        float acc = 0.f;
        #pragma unroll
        for (int i = 0; i < 8; i++) acc += sh[i];
        bcast = acc;
    }
    __syncthreads();
    const float invs = 1.0f / bcast;

    for (int i = tid; i < len; i += 256) {
        bf16 h, l;
        cvt_split(s[i] * invs, h, l);
        ph[i] = h; pl[i] = l;
    }
    const bf16 z = __float2bfloat16(0.f);
    for (int i = len + tid; i < zlim; i += 256) { ph[i] = z; pl[i] = z; }
}

// ---------------------------------------------------------------------------
// kernel_launch: x, Wq, bq, Wk, bk, Wv, bv, Wo, bo
// ---------------------------------------------------------------------------
extern "C" void kernel_launch(void* const* d_in, const int* in_sizes, int n_in,
                              void* d_out, int out_size)
{
    const float* x  = (const float*)d_in[0];
    const float* Wq = (const float*)d_in[1];
    const float* bq = (const float*)d_in[2];
    const float* Wk = (const float*)d_in[3];
    const float* bk = (const float*)d_in[4];
    const float* Wv = (const float*)d_in[5];
    const float* bv = (const float*)d_in[6];
    const float* Wo = (const float*)d_in[7];
    const float* bo = (const float*)d_in[8];
    float* out = (float*)d_out;

    bf16 *xh, *xl, *Wqh, *Wql, *Wkh, *Wkl, *Wvh, *Wvl, *Woh, *Wol;
    bf16 *Qh, *Ql, *Kh, *Kl, *Vh, *Vl, *Oh, *Ol, *Ph, *Pl;
    float* pS;
    cudaGetSymbolAddress((void**)&xh, g_xh);   cudaGetSymbolAddress((void**)&xl, g_xl);
    cudaGetSymbolAddress((void**)&Wqh, g_Wqh); cudaGetSymbolAddress((void**)&Wql, g_Wql);
    cudaGetSymbolAddress((void**)&Wkh, g_Wkh); cudaGetSymbolAddress((void**)&Wkl, g_Wkl);
    cudaGetSymbolAddress((void**)&Wvh, g_Wvh); cudaGetSymbolAddress((void**)&Wvl, g_Wvl);
    cudaGetSymbolAddress((void**)&Woh, g_Woh); cudaGetSymbolAddress((void**)&Wol, g_Wol);
    cudaGetSymbolAddress((void**)&Qh, g_Qh);   cudaGetSymbolAddress((void**)&Ql, g_Ql);
    cudaGetSymbolAddress((void**)&Kh, g_Kh);   cudaGetSymbolAddress((void**)&Kl, g_Kl);
    cudaGetSymbolAddress((void**)&Vh, g_Vh);   cudaGetSymbolAddress((void**)&Vl, g_Vl);
    cudaGetSymbolAddress((void**)&Oh, g_Oh);   cudaGetSymbolAddress((void**)&Ol, g_Ol);
    cudaGetSymbolAddress((void**)&Ph, g_Ph);   cudaGetSymbolAddress((void**)&Pl, g_Pl);
    cudaGetSymbolAddress((void**)&pS, g_S);

    const int B = BATCH, T = SEQ, C = CH, M = MTOT;
    const long long sTC = (long long)T * C;
    const long long sTT = (long long)T * T;

    cudaFuncSetAttribute(gemm_bf3<true,  true,  false, false, true >, cudaFuncAttributeMaxDynamicSharedMemorySize, SMEM_TOTAL);
    cudaFuncSetAttribute(gemm_bf3<true,  false, false, false, true >, cudaFuncAttributeMaxDynamicSharedMemorySize, SMEM_TOTAL);
    cudaFuncSetAttribute(gemm_bf3<false, false, true,  false, false>, cudaFuncAttributeMaxDynamicSharedMemorySize, SMEM_TOTAL);
    cudaFuncSetAttribute(gemm_bf3<true,  false, false, true,  true >, cudaFuncAttributeMaxDynamicSharedMemorySize, SMEM_TOTAL);
    cudaFuncSetAttribute(gemm_bf3<true,  false, false, false, false>, cudaFuncAttributeMaxDynamicSharedMemorySize, SMEM_TOTAL);

    // split inputs once
    split_f32<<<(M * C / 4 + 255) / 256, 256>>>(x, xh, xl, M * C);
    split_f32<<<(C * C / 4 + 255) / 256, 256>>>(Wq, Wqh, Wql, C * C);
    split_f32<<<(C * C / 4 + 255) / 256, 256>>>(Wk, Wkh, Wkl, C * C);
    split_f32<<<(C * C / 4 + 255) / 256, 256>>>(Wv, Wvh, Wvl, C * C);
    split_f32<<<(C * C / 4 + 255) / 256, 256>>>(Wo, Woh, Wol, C * C);

    dim3 blk(NTHREADS);
    dim3 gridProj(C / TILE_N, M / TILE_M, 1);
    dim3 gridS(T / TILE_N, T / TILE_M, B);
    dim3 gridPV(C / TILE_N, T / TILE_M, B);

    // Q/K/V projections (RoPE fused into Q/K), hi/lo outputs
    gemm_bf3<true, true,  false, false, true><<<gridProj, blk, SMEM_TOTAL>>>(
        xh, xl, Wqh, Wql, bq, nullptr, Qh, Ql, M, C, C, 0, 0, 0, 1.0f);
    gemm_bf3<true, true,  false, false, true><<<gridProj, blk, SMEM_TOTAL>>>(
        xh, xl, Wkh, Wkl, bk, nullptr, Kh, Kl, M, C, C, 0, 0, 0, 1.0f);
    gemm_bf3<true, false, false, false, true><<<gridProj, blk, SMEM_TOTAL>>>(
        xh, xl, Wvh, Wvl, bv, nullptr, Vh, Vl, M, C, C, 0, 0, 0, 1.0f);

    // S = Q K^T / 32 (fp32 out, causal block skip)
    gemm_bf3<false, false, true, false, false><<<gridS, blk, SMEM_TOTAL>>>(
        Qh, Ql, Kh, Kl, nullptr, pS, nullptr, nullptr, T, T, C, sTC, sTC, sTT, 0.03125f);

    softmax_split<<<B * T, blk>>>(pS, Ph, Pl, T);

    // O = P V (K truncated at causal boundary), hi/lo out
    gemm_bf3<true, false, false, true, true><<<gridPV, blk, SMEM_TOTAL>>>(
        Ph, Pl, Vh, Vl, nullptr, nullptr, Oh, Ol, T, C, T, sTT, sTC, sTC, 1.0f);

    // out = O Wo + bo (fp32)
    gemm_bf3<true, false, false, false, false><<<gridProj, blk, SMEM_TOTAL>>>(
        Oh, Ol, Woh, Wol, bo, out, nullptr, nullptr, M, C, C, 0, 0, 0, 1.0f);
}